// round 5
// baseline (speedup 1.0000x reference)
#include <cuda_runtime.h>
#include <cuda_bf16.h>

#define N_NODES 50000
#define N_EDGES 1200000
#define DIM 64

// Scratch (allocation-free __device__ globals)
__device__ __align__(16) float g_Henc[N_NODES * DIM];        // encoder output (fp32, upd input)
__device__ __align__(16) unsigned int g_Hb[N_NODES * DIM/2]; // bf16x2 copy of Henc (gather source)
__device__ __align__(16) float g_agg [N_NODES * DIM];        // pulled aggregation
__device__ __align__(16) int   g_deg [N_NODES];              // out-degree over u
__device__ __align__(16) int   g_cnt [N_NODES];              // in-degree over v
__device__ __align__(16) int   g_fill[N_NODES];              // fill cursor per v
__device__ __align__(16) int   g_rowstart[N_NODES + 1];      // CSR row offsets (by v)
__device__ __align__(16) int2  g_uv  [N_EDGES];              // decoded (u,v)
__device__ __align__(16) int2  g_csr [N_EDGES];              // (u, bits(norm)) sorted by v
__device__ __align__(16) float g_sum64[DIM];
__device__ int g_is32;   // 1 if edge_index is int32 on device, 0 if int64

// ---------------------------------------------------------------------------
// Init: block 0 probes edge_index dtype; all blocks zero counters/sums.
__global__ void __launch_bounds__(256) k_init(const unsigned long long* __restrict__ ei) {
    int i = blockIdx.x * 256 + threadIdx.x;
    if (i < N_NODES) { g_deg[i] = 0; g_cnt[i] = 0; g_fill[i] = 0; }
    if (i < DIM)     g_sum64[i] = 0.f;
    if (blockIdx.x == 0) {
        int t = threadIdx.x;
        unsigned int any = 0;
        for (int j = t; j < 2048; j += 256)
            any |= (unsigned int)(ei[j] >> 32);
        __shared__ unsigned int s;
        if (t == 0) s = 0u;
        __syncthreads();
        atomicOr(&s, any);
        __syncthreads();
        if (t == 0) g_is32 = (s != 0u) ? 1 : 0;
    }
}

// Decode edge index -> int2 uv, histogram out-degree(u) and in-degree(v)
__global__ void __launch_bounds__(256) k_prep(const void* __restrict__ eiv) {
    int i = blockIdx.x * 256 + threadIdx.x;
    if (i >= N_EDGES) return;
    int uu, vv;
    if (g_is32) {
        const int* e = (const int*)eiv;
        uu = e[i];
        vv = e[N_EDGES + i];
    } else {
        const long long* e = (const long long*)eiv;
        uu = (int)e[i];
        vv = (int)e[N_EDGES + i];
    }
    uu = min(max(uu, 0), N_NODES - 1);
    vv = min(max(vv, 0), N_NODES - 1);
    g_uv[i] = make_int2(uu, vv);
    atomicAdd(&g_deg[uu], 1);
    atomicAdd(&g_cnt[vv], 1);
}

// One-block exclusive scan of g_cnt -> g_rowstart
__global__ void __launch_bounds__(1024) k_scan() {
    const int CH = (N_NODES + 1023) / 1024;  // 49
    __shared__ int sh[1024];
    int t = threadIdx.x;
    int base = t * CH;
    int tot = 0;
    for (int i = 0; i < CH; i++) {
        int j = base + i;
        if (j < N_NODES) tot += g_cnt[j];
    }
    sh[t] = tot;
    __syncthreads();
    for (int o = 1; o < 1024; o <<= 1) {
        int v = (t >= o) ? sh[t - o] : 0;
        __syncthreads();
        sh[t] += v;
        __syncthreads();
    }
    int run = (t > 0) ? sh[t - 1] : 0;
    for (int i = 0; i < CH; i++) {
        int j = base + i;
        if (j < N_NODES) {
            g_rowstart[j] = run;
            run += g_cnt[j];
        }
    }
    if (t == 1023) g_rowstart[N_NODES] = run;
}

// Scatter edges into CSR slots (sorted by v); w = ((deg_u+1)(deg_v+1))^-1/2
__global__ void __launch_bounds__(256) k_fill() {
    int i = blockIdx.x * 256 + threadIdx.x;
    if (i >= N_EDGES) return;
    int2 uv = g_uv[i];
    float du = (float)(g_deg[uv.x] + 1);
    float dv = (float)(g_deg[uv.y] + 1);
    float w = rsqrtf(du * dv);
    int pos = g_rowstart[uv.y] + atomicAdd(&g_fill[uv.y], 1);
    g_csr[pos] = make_int2(uv.x, __float_as_int(w));
}

// ---------------------------------------------------------------------------
// Core 64x64 row GEMM: x (16 float4) @ Ws + Bs -> acc (16 float4)
__device__ __forceinline__ void gemm64(
    const float4* __restrict__ x, const float4* __restrict__ Ws,
    const float* __restrict__ Bs, float4* __restrict__ acc)
{
#pragma unroll
    for (int j = 0; j < 16; j++)
        acc[j] = make_float4(Bs[4*j], Bs[4*j+1], Bs[4*j+2], Bs[4*j+3]);
#pragma unroll 1
    for (int kk = 0; kk < 16; kk++) {
        float4 hv = x[kk];
#pragma unroll
        for (int kc = 0; kc < 4; kc++) {
            float hk = (kc == 0) ? hv.x : (kc == 1) ? hv.y : (kc == 2) ? hv.z : hv.w;
            const float4* wrow = Ws + (kk * 4 + kc) * 16;
#pragma unroll
            for (int j = 0; j < 16; j++) {
                float4 w = wrow[j];
                acc[j].x = fmaf(hk, w.x, acc[j].x);
                acc[j].y = fmaf(hk, w.y, acc[j].y);
                acc[j].z = fmaf(hk, w.z, acc[j].z);
                acc[j].w = fmaf(hk, w.w, acc[j].w);
            }
        }
    }
}

__device__ __forceinline__ void store_row_f32_bf16(int row, const float4* acc) {
    float4* o32 = (float4*)(g_Henc + row * DIM);
    uint2*  ob  = (uint2*)(g_Hb + row * (DIM/2));
#pragma unroll
    for (int j = 0; j < 16; j++) {
        float4 v = acc[j];
        o32[j] = v;
        __nv_bfloat162 b0 = __floats2bfloat162_rn(v.x, v.y);
        __nv_bfloat162 b1 = __floats2bfloat162_rn(v.z, v.w);
        ob[j] = make_uint2(*(unsigned int*)&b0, *(unsigned int*)&b1);
    }
}

// Layer-0 encoder: g_Henc/g_Hb = X @ W + b
__global__ void __launch_bounds__(128) k_enc0(
    const float* __restrict__ X,
    const float* __restrict__ W,
    const float* __restrict__ B)
{
    __shared__ float4 Ws[1024];
    __shared__ float  Bs[64];
    int tid = threadIdx.x;
    const float4* W4 = (const float4*)W;
#pragma unroll
    for (int i = 0; i < 8; i++) Ws[tid + 128 * i] = W4[tid + 128 * i];
    if (tid < 64) Bs[tid] = B[tid];
    __syncthreads();

    int row = blockIdx.x * 128 + tid;
    if (row >= N_NODES) return;
    float4 acc[16];
    gemm64((const float4*)(X + row * DIM), Ws, Bs, acc);
    store_row_f32_bf16(row, acc);
}

// Fused update + next-layer encoder:
//   h = relu((agg + Henc) @ Wu + bu);  Henc' = h @ We + be  (fp32 + bf16)
__global__ void __launch_bounds__(128) k_upd_enc(
    const float* __restrict__ Wu, const float* __restrict__ Bu,
    const float* __restrict__ We, const float* __restrict__ Be)
{
    __shared__ float4 Wsu[1024], Wse[1024];
    __shared__ float  Bsu[64],  Bse[64];
    int tid = threadIdx.x;
    const float4* Wu4 = (const float4*)Wu;
    const float4* We4 = (const float4*)We;
#pragma unroll
    for (int i = 0; i < 8; i++) {
        Wsu[tid + 128 * i] = Wu4[tid + 128 * i];
        Wse[tid + 128 * i] = We4[tid + 128 * i];
    }
    if (tid < 64) { Bsu[tid] = Bu[tid]; Bse[tid] = Be[tid]; }
    __syncthreads();

    int row = blockIdx.x * 128 + tid;
    if (row >= N_NODES) return;

    // sum input: Henc + agg
    float4 x[16];
    const float4* hr = (const float4*)(g_Henc + row * DIM);
    const float4* ar = (const float4*)(g_agg  + row * DIM);
#pragma unroll
    for (int j = 0; j < 16; j++) {
        float4 a = hr[j], b = ar[j];
        x[j] = make_float4(a.x + b.x, a.y + b.y, a.z + b.z, a.w + b.w);
    }
    float4 h[16];
    gemm64(x, Wsu, Bsu, h);
#pragma unroll
    for (int j = 0; j < 16; j++) {
        h[j].x = fmaxf(h[j].x, 0.f); h[j].y = fmaxf(h[j].y, 0.f);
        h[j].z = fmaxf(h[j].z, 0.f); h[j].w = fmaxf(h[j].w, 0.f);
    }
    float4 acc[16];
    gemm64(h, Wse, Bse, acc);
    store_row_f32_bf16(row, acc);
}

// Final update + readout: h = relu((agg+Henc)@Wu+bu); g_sum64 += column-sums(h)
__global__ void __launch_bounds__(128) k_upd_sum(
    const float* __restrict__ Wu, const float* __restrict__ Bu)
{
    __shared__ float4 Wsu[1024];
    __shared__ float  Bsu[64];
    __shared__ float  ssum[64];
    int tid = threadIdx.x;
    const float4* Wu4 = (const float4*)Wu;
#pragma unroll
    for (int i = 0; i < 8; i++) Wsu[tid + 128 * i] = Wu4[tid + 128 * i];
    if (tid < 64) { Bsu[tid] = Bu[tid]; ssum[tid] = 0.f; }
    __syncthreads();

    int row = blockIdx.x * 128 + tid;
    bool valid = (row < N_NODES);

    float4 h[16];
    if (valid) {
        float4 x[16];
        const float4* hr = (const float4*)(g_Henc + row * DIM);
        const float4* ar = (const float4*)(g_agg  + row * DIM);
#pragma unroll
        for (int j = 0; j < 16; j++) {
            float4 a = hr[j], b = ar[j];
            x[j] = make_float4(a.x + b.x, a.y + b.y, a.z + b.z, a.w + b.w);
        }
        gemm64(x, Wsu, Bsu, h);
#pragma unroll
        for (int j = 0; j < 16; j++) {
            h[j].x = fmaxf(h[j].x, 0.f); h[j].y = fmaxf(h[j].y, 0.f);
            h[j].z = fmaxf(h[j].z, 0.f); h[j].w = fmaxf(h[j].w, 0.f);
        }
    } else {
#pragma unroll
        for (int j = 0; j < 16; j++) h[j] = make_float4(0.f, 0.f, 0.f, 0.f);
    }

    // butterfly-reduce each of the 64 columns across the warp
    int lane = tid & 31;
#pragma unroll
    for (int j = 0; j < 16; j++) {
#pragma unroll
        for (int kc = 0; kc < 4; kc++) {
            float v = (kc == 0) ? h[j].x : (kc == 1) ? h[j].y : (kc == 2) ? h[j].z : h[j].w;
#pragma unroll
            for (int o = 16; o; o >>= 1) v += __shfl_xor_sync(0xffffffffu, v, o);
            if (lane == 0) atomicAdd(&ssum[4 * j + kc], v);
        }
    }
    __syncthreads();
    if (tid < 64) atomicAdd(&g_sum64[tid], ssum[tid]);
}

// ---------------------------------------------------------------------------
// Pull aggregation (bf16 gather): agg[v] = sum_e w_e * Hb[u_e]
__global__ void __launch_bounds__(256) k_agg() {
    int idx = blockIdx.x * 256 + threadIdx.x;
    int node = idx >> 4;
    if (node >= N_NODES) return;
    int c = idx & 15;
    int s = g_rowstart[node];
    int e = g_rowstart[node + 1];
    float4 acc = make_float4(0.f, 0.f, 0.f, 0.f);
    const uint2* __restrict__ Hb = (const uint2*)g_Hb;

    int i = s;
    for (; i + 2 <= e; i += 2) {
        int2 e0 = g_csr[i];
        int2 e1 = g_csr[i + 1];
        uint2 p0 = Hb[e0.x * 16 + c];
        uint2 p1 = Hb[e1.x * 16 + c];
        float w0 = __int_as_float(e0.y);
        float w1 = __int_as_float(e1.y);
        float2 a0 = __bfloat1622float2(*(__nv_bfloat162*)&p0.x);
        float2 a1 = __bfloat1622float2(*(__nv_bfloat162*)&p0.y);
        float2 b0 = __bfloat1622float2(*(__nv_bfloat162*)&p1.x);
        float2 b1 = __bfloat1622float2(*(__nv_bfloat162*)&p1.y);
        acc.x = fmaf(w0, a0.x, fmaf(w1, b0.x, acc.x));
        acc.y = fmaf(w0, a0.y, fmaf(w1, b0.y, acc.y));
        acc.z = fmaf(w0, a1.x, fmaf(w1, b1.x, acc.z));
        acc.w = fmaf(w0, a1.y, fmaf(w1, b1.y, acc.w));
    }
    if (i < e) {
        int2 e0 = g_csr[i];
        uint2 p0 = Hb[e0.x * 16 + c];
        float w0 = __int_as_float(e0.y);
        float2 a0 = __bfloat1622float2(*(__nv_bfloat162*)&p0.x);
        float2 a1 = __bfloat1622float2(*(__nv_bfloat162*)&p0.y);
        acc.x = fmaf(w0, a0.x, acc.x);
        acc.y = fmaf(w0, a0.y, acc.y);
        acc.z = fmaf(w0, a1.x, acc.z);
        acc.w = fmaf(w0, a1.y, acc.w);
    }
    ((float4*)g_agg)[node * 16 + c] = acc;
}

// out[0] = dot(sum64, out_w)/N + out_b
__global__ void k_final(const float* __restrict__ out_w,
                        const float* __restrict__ out_b,
                        float* __restrict__ out)
{
    int t = threadIdx.x;  // 32 threads
    float p = g_sum64[t] * out_w[t] + g_sum64[t + 32] * out_w[t + 32];
#pragma unroll
    for (int o = 16; o; o >>= 1) p += __shfl_down_sync(0xffffffffu, p, o);
    if (t == 0) out[0] = p / (float)N_NODES + out_b[0];
}

// ---------------------------------------------------------------------------
extern "C" void kernel_launch(void* const* d_in, const int* in_sizes, int n_in,
                              void* d_out, int out_size)
{
    const float* H  = (const float*)d_in[0];
    const void*  ei = d_in[1];
    // d_in[2] = E (unused by reference GCN path)
    const float* enc_w[3] = {(const float*)d_in[3],  (const float*)d_in[7],  (const float*)d_in[11]};
    const float* enc_b[3] = {(const float*)d_in[4],  (const float*)d_in[8],  (const float*)d_in[12]};
    const float* upd_w[3] = {(const float*)d_in[5],  (const float*)d_in[9],  (const float*)d_in[13]};
    const float* upd_b[3] = {(const float*)d_in[6],  (const float*)d_in[10], (const float*)d_in[14]};
    const float* out_w = (const float*)d_in[15];
    const float* out_b = (const float*)d_in[16];
    float* out = (float*)d_out;

    const int EB = (N_EDGES + 255) / 256;             // 4688
    const int NB = (N_NODES + 255) / 256;             // 196
    const int GB = (N_NODES + 127) / 128;             // 391
    const int AB = (N_NODES * 16 + 255) / 256;        // 3125

    k_init<<<NB, 256>>>((const unsigned long long*)ei);
    k_prep<<<EB, 256>>>(ei);
    k_scan<<<1, 1024>>>();
    k_fill<<<EB, 256>>>();

    k_enc0<<<GB, 128>>>(H, enc_w[0], enc_b[0]);
    k_agg <<<AB, 256>>>();
    k_upd_enc<<<GB, 128>>>(upd_w[0], upd_b[0], enc_w[1], enc_b[1]);
    k_agg <<<AB, 256>>>();
    k_upd_enc<<<GB, 128>>>(upd_w[1], upd_b[1], enc_w[2], enc_b[2]);
    k_agg <<<AB, 256>>>();
    k_upd_sum<<<GB, 128>>>(upd_w[2], upd_b[2]);

    k_final<<<1, 32>>>(out_w, out_b, out);
}

// round 6
// speedup vs baseline: 1.0098x; 1.0098x over previous
#include <cuda_runtime.h>
#include <cuda_bf16.h>

#define N_NODES 50000
#define N_EDGES 1200000
#define DIM 64

// Scratch (allocation-free __device__ globals)
__device__ __align__(16) float g_Henc[N_NODES * DIM];        // encoder output (fp32)
__device__ __align__(16) unsigned int g_Hb[N_NODES * DIM/2]; // bf16x2 copy of Henc (gather src)
__device__ __align__(16) float g_agg [N_NODES * DIM];        // pulled aggregation
__device__ __align__(16) float g_H   [N_NODES * DIM];        // layer output (fp32)
__device__ __align__(16) int   g_deg [N_NODES];              // out-degree over u
__device__ __align__(16) int   g_cnt [N_NODES];              // in-degree over v
__device__ __align__(16) int   g_fill[N_NODES];              // fill cursor per v
__device__ __align__(16) int   g_rowstart[N_NODES + 1];      // CSR row offsets (by v)
__device__ __align__(16) int2  g_uv  [N_EDGES];              // decoded (u,v)
__device__ __align__(16) int2  g_csr [N_EDGES];              // (u, bits(norm)) sorted by v
__device__ __align__(16) float g_sum64[DIM];
__device__ int g_is32;   // 1 if edge_index is int32 on device, 0 if int64

// ---------------------------------------------------------------------------
// Init: block 0 probes edge_index dtype; all blocks zero counters/sums.
__global__ void __launch_bounds__(256) k_init(const unsigned long long* __restrict__ ei) {
    int i = blockIdx.x * 256 + threadIdx.x;
    if (i < N_NODES) { g_deg[i] = 0; g_cnt[i] = 0; g_fill[i] = 0; }
    if (i < DIM)     g_sum64[i] = 0.f;
    if (blockIdx.x == 0) {
        int t = threadIdx.x;
        unsigned int any = 0;
        for (int j = t; j < 2048; j += 256)
            any |= (unsigned int)(ei[j] >> 32);
        __shared__ unsigned int s;
        if (t == 0) s = 0u;
        __syncthreads();
        atomicOr(&s, any);
        __syncthreads();
        if (t == 0) g_is32 = (s != 0u) ? 1 : 0;
    }
}

// Decode edge index -> int2 uv, histogram out-degree(u) and in-degree(v)
__global__ void __launch_bounds__(256) k_prep(const void* __restrict__ eiv) {
    int i = blockIdx.x * 256 + threadIdx.x;
    if (i >= N_EDGES) return;
    int uu, vv;
    if (g_is32) {
        const int* e = (const int*)eiv;
        uu = e[i];
        vv = e[N_EDGES + i];
    } else {
        const long long* e = (const long long*)eiv;
        uu = (int)e[i];
        vv = (int)e[N_EDGES + i];
    }
    uu = min(max(uu, 0), N_NODES - 1);
    vv = min(max(vv, 0), N_NODES - 1);
    g_uv[i] = make_int2(uu, vv);
    atomicAdd(&g_deg[uu], 1);
    atomicAdd(&g_cnt[vv], 1);
}

// One-block exclusive scan of g_cnt -> g_rowstart
__global__ void __launch_bounds__(1024) k_scan() {
    const int CH = (N_NODES + 1023) / 1024;  // 49
    __shared__ int sh[1024];
    int t = threadIdx.x;
    int base = t * CH;
    int tot = 0;
    for (int i = 0; i < CH; i++) {
        int j = base + i;
        if (j < N_NODES) tot += g_cnt[j];
    }
    sh[t] = tot;
    __syncthreads();
    for (int o = 1; o < 1024; o <<= 1) {
        int v = (t >= o) ? sh[t - o] : 0;
        __syncthreads();
        sh[t] += v;
        __syncthreads();
    }
    int run = (t > 0) ? sh[t - 1] : 0;
    for (int i = 0; i < CH; i++) {
        int j = base + i;
        if (j < N_NODES) {
            g_rowstart[j] = run;
            run += g_cnt[j];
        }
    }
    if (t == 1023) g_rowstart[N_NODES] = run;
}

// Scatter edges into CSR slots (sorted by v); w = ((deg_u+1)(deg_v+1))^-1/2
__global__ void __launch_bounds__(256) k_fill() {
    int i = blockIdx.x * 256 + threadIdx.x;
    if (i >= N_EDGES) return;
    int2 uv = g_uv[i];
    float du = (float)(g_deg[uv.x] + 1);
    float dv = (float)(g_deg[uv.y] + 1);
    float w = rsqrtf(du * dv);
    int pos = g_rowstart[uv.y] + atomicAdd(&g_fill[uv.y], 1);
    g_csr[pos] = make_int2(uv.x, __float_as_int(w));
}

// ---------------------------------------------------------------------------
// Core 64x64 row GEMM: x (16 float4) @ Ws + Bs -> acc (16 float4)
__device__ __forceinline__ void gemm64(
    const float4* __restrict__ x, const float4* __restrict__ Ws,
    const float* __restrict__ Bs, float4* __restrict__ acc)
{
#pragma unroll
    for (int j = 0; j < 16; j++)
        acc[j] = make_float4(Bs[4*j], Bs[4*j+1], Bs[4*j+2], Bs[4*j+3]);
#pragma unroll 1
    for (int kk = 0; kk < 16; kk++) {
        float4 hv = x[kk];
#pragma unroll
        for (int kc = 0; kc < 4; kc++) {
            float hk = (kc == 0) ? hv.x : (kc == 1) ? hv.y : (kc == 2) ? hv.z : hv.w;
            const float4* wrow = Ws + (kk * 4 + kc) * 16;
#pragma unroll
            for (int j = 0; j < 16; j++) {
                float4 w = wrow[j];
                acc[j].x = fmaf(hk, w.x, acc[j].x);
                acc[j].y = fmaf(hk, w.y, acc[j].y);
                acc[j].z = fmaf(hk, w.z, acc[j].z);
                acc[j].w = fmaf(hk, w.w, acc[j].w);
            }
        }
    }
}

// Encoder GEMM: g_Henc/g_Hb = src @ W + b. src = X (layer 0) or g_H.
__global__ void __launch_bounds__(128) k_enc(
    const float* __restrict__ X,
    const float* __restrict__ W,
    const float* __restrict__ B,
    int use_gH)
{
    __shared__ float4 Ws[1024];
    __shared__ float  Bs[64];
    int tid = threadIdx.x;
    const float4* W4 = (const float4*)W;
#pragma unroll
    for (int i = 0; i < 8; i++) Ws[tid + 128 * i] = W4[tid + 128 * i];
    if (tid < 64) Bs[tid] = B[tid];
    __syncthreads();

    int row = blockIdx.x * 128 + tid;
    if (row >= N_NODES) return;
    const float* src = use_gH ? g_H : X;
    float4 acc[16];
    gemm64((const float4*)(src + row * DIM), Ws, Bs, acc);

    float4* o32 = (float4*)(g_Henc + row * DIM);
    uint2*  ob  = (uint2*)(g_Hb + row * (DIM/2));
#pragma unroll
    for (int j = 0; j < 16; j++) {
        float4 v = acc[j];
        o32[j] = v;
        __nv_bfloat162 b0 = __floats2bfloat162_rn(v.x, v.y);
        __nv_bfloat162 b1 = __floats2bfloat162_rn(v.z, v.w);
        ob[j] = make_uint2(*(unsigned int*)&b0, *(unsigned int*)&b1);
    }
}

// Update GEMM: g_H = relu((g_agg + g_Henc) @ W + b)
__global__ void __launch_bounds__(128) k_upd(
    const float* __restrict__ W,
    const float* __restrict__ B)
{
    __shared__ float4 Ws[1024];
    __shared__ float  Bs[64];
    int tid = threadIdx.x;
    const float4* W4 = (const float4*)W;
#pragma unroll
    for (int i = 0; i < 8; i++) Ws[tid + 128 * i] = W4[tid + 128 * i];
    if (tid < 64) Bs[tid] = B[tid];
    __syncthreads();

    int row = blockIdx.x * 128 + tid;
    if (row >= N_NODES) return;

    float4 x[16];
    const float4* hr = (const float4*)(g_Henc + row * DIM);
    const float4* ar = (const float4*)(g_agg  + row * DIM);
#pragma unroll
    for (int j = 0; j < 16; j++) {
        float4 a = hr[j], b = ar[j];
        x[j] = make_float4(a.x + b.x, a.y + b.y, a.z + b.z, a.w + b.w);
    }
    float4 acc[16];
    gemm64(x, Ws, Bs, acc);

    float4* o = (float4*)(g_H + row * DIM);
#pragma unroll
    for (int j = 0; j < 16; j++) {
        float4 v = acc[j];
        v.x = fmaxf(v.x, 0.f); v.y = fmaxf(v.y, 0.f);
        v.z = fmaxf(v.z, 0.f); v.w = fmaxf(v.w, 0.f);
        o[j] = v;
    }
}

// Final update + readout: h = relu((agg+Henc)@Wu+bu); g_sum64 += column-sums(h)
__global__ void __launch_bounds__(128) k_upd_sum(
    const float* __restrict__ Wu, const float* __restrict__ Bu)
{
    __shared__ float4 Wsu[1024];
    __shared__ float  Bsu[64];
    __shared__ float  ssum[64];
    int tid = threadIdx.x;
    const float4* Wu4 = (const float4*)Wu;
#pragma unroll
    for (int i = 0; i < 8; i++) Wsu[tid + 128 * i] = Wu4[tid + 128 * i];
    if (tid < 64) { Bsu[tid] = Bu[tid]; ssum[tid] = 0.f; }
    __syncthreads();

    int row = blockIdx.x * 128 + tid;
    bool valid = (row < N_NODES);

    float4 h[16];
    if (valid) {
        float4 x[16];
        const float4* hr = (const float4*)(g_Henc + row * DIM);
        const float4* ar = (const float4*)(g_agg  + row * DIM);
#pragma unroll
        for (int j = 0; j < 16; j++) {
            float4 a = hr[j], b = ar[j];
            x[j] = make_float4(a.x + b.x, a.y + b.y, a.z + b.z, a.w + b.w);
        }
        gemm64(x, Wsu, Bsu, h);
#pragma unroll
        for (int j = 0; j < 16; j++) {
            h[j].x = fmaxf(h[j].x, 0.f); h[j].y = fmaxf(h[j].y, 0.f);
            h[j].z = fmaxf(h[j].z, 0.f); h[j].w = fmaxf(h[j].w, 0.f);
        }
    } else {
#pragma unroll
        for (int j = 0; j < 16; j++) h[j] = make_float4(0.f, 0.f, 0.f, 0.f);
    }

    int lane = tid & 31;
#pragma unroll
    for (int j = 0; j < 16; j++) {
#pragma unroll
        for (int kc = 0; kc < 4; kc++) {
            float v = (kc == 0) ? h[j].x : (kc == 1) ? h[j].y : (kc == 2) ? h[j].z : h[j].w;
#pragma unroll
            for (int o = 16; o; o >>= 1) v += __shfl_xor_sync(0xffffffffu, v, o);
            if (lane == 0) atomicAdd(&ssum[4 * j + kc], v);
        }
    }
    __syncthreads();
    if (tid < 64) atomicAdd(&g_sum64[tid], ssum[tid]);
}

// ---------------------------------------------------------------------------
// bf16x2-pair FMA helper
__device__ __forceinline__ void bf16fma(float4& a, int wbits, uint2 p) {
    float w = __int_as_float(wbits);
    float2 lo = __bfloat1622float2(*(__nv_bfloat162*)&p.x);
    float2 hi = __bfloat1622float2(*(__nv_bfloat162*)&p.y);
    a.x = fmaf(w, lo.x, a.x); a.y = fmaf(w, lo.y, a.y);
    a.z = fmaf(w, hi.x, a.z); a.w = fmaf(w, hi.y, a.w);
}

// Pull aggregation (bf16 gather, unroll-4 / 4 accumulator chains for MLP):
// agg[v] = sum_e w_e * Hb[u_e]
__global__ void __launch_bounds__(256) k_agg() {
    int idx = blockIdx.x * 256 + threadIdx.x;
    int node = idx >> 4;
    if (node >= N_NODES) return;
    int c = idx & 15;
    int s = g_rowstart[node];
    int e = g_rowstart[node + 1];
    const uint2* __restrict__ Hb = (const uint2*)g_Hb;

    float4 a0 = make_float4(0.f, 0.f, 0.f, 0.f);
    float4 a1 = make_float4(0.f, 0.f, 0.f, 0.f);
    float4 a2 = make_float4(0.f, 0.f, 0.f, 0.f);
    float4 a3 = make_float4(0.f, 0.f, 0.f, 0.f);

    int i = s;
    for (; i + 4 <= e; i += 4) {
        int2 e0 = g_csr[i];
        int2 e1 = g_csr[i + 1];
        int2 e2 = g_csr[i + 2];
        int2 e3 = g_csr[i + 3];
        uint2 p0 = Hb[e0.x * 16 + c];
        uint2 p1 = Hb[e1.x * 16 + c];
        uint2 p2 = Hb[e2.x * 16 + c];
        uint2 p3 = Hb[e3.x * 16 + c];
        bf16fma(a0, e0.y, p0);
        bf16fma(a1, e1.y, p1);
        bf16fma(a2, e2.y, p2);
        bf16fma(a3, e3.y, p3);
    }
    for (; i < e; i++) {
        int2 e0 = g_csr[i];
        uint2 p0 = Hb[e0.x * 16 + c];
        bf16fma(a0, e0.y, p0);
    }

    float4 acc;
    acc.x = (a0.x + a1.x) + (a2.x + a3.x);
    acc.y = (a0.y + a1.y) + (a2.y + a3.y);
    acc.z = (a0.z + a1.z) + (a2.z + a3.z);
    acc.w = (a0.w + a1.w) + (a2.w + a3.w);
    ((float4*)g_agg)[node * 16 + c] = acc;
}

// out[0] = dot(sum64, out_w)/N + out_b
__global__ void k_final(const float* __restrict__ out_w,
                        const float* __restrict__ out_b,
                        float* __restrict__ out)
{
    int t = threadIdx.x;  // 32 threads
    float p = g_sum64[t] * out_w[t] + g_sum64[t + 32] * out_w[t + 32];
#pragma unroll
    for (int o = 16; o; o >>= 1) p += __shfl_down_sync(0xffffffffu, p, o);
    if (t == 0) out[0] = p / (float)N_NODES + out_b[0];
}

// ---------------------------------------------------------------------------
extern "C" void kernel_launch(void* const* d_in, const int* in_sizes, int n_in,
                              void* d_out, int out_size)
{
    const float* H  = (const float*)d_in[0];
    const void*  ei = d_in[1];
    // d_in[2] = E (unused by reference GCN path)
    const float* enc_w[3] = {(const float*)d_in[3],  (const float*)d_in[7],  (const float*)d_in[11]};
    const float* enc_b[3] = {(const float*)d_in[4],  (const float*)d_in[8],  (const float*)d_in[12]};
    const float* upd_w[3] = {(const float*)d_in[5],  (const float*)d_in[9],  (const float*)d_in[13]};
    const float* upd_b[3] = {(const float*)d_in[6],  (const float*)d_in[10], (const float*)d_in[14]};
    const float* out_w = (const float*)d_in[15];
    const float* out_b = (const float*)d_in[16];
    float* out = (float*)d_out;

    const int EB = (N_EDGES + 255) / 256;             // 4688
    const int NB = (N_NODES + 255) / 256;             // 196
    const int GB = (N_NODES + 127) / 128;             // 391
    const int AB = (N_NODES * 16 + 255) / 256;        // 3125

    k_init<<<NB, 256>>>((const unsigned long long*)ei);
    k_prep<<<EB, 256>>>(ei);
    k_scan<<<1, 1024>>>();
    k_fill<<<EB, 256>>>();

    for (int l = 0; l < 3; l++) {
        k_enc<<<GB, 128>>>(H, enc_w[l], enc_b[l], l > 0 ? 1 : 0);
        k_agg<<<AB, 256>>>();
        if (l < 2) k_upd<<<GB, 128>>>(upd_w[l], upd_b[l]);
        else       k_upd_sum<<<GB, 128>>>(upd_w[l], upd_b[l]);
    }

    k_final<<<1, 32>>>(out_w, out_b, out);
}

// round 7
// speedup vs baseline: 1.1547x; 1.1434x over previous
#include <cuda_runtime.h>
#include <cuda_bf16.h>

#define N_NODES 50000
#define N_EDGES 1200000
#define DIM 64
#define SCAN_B 49   // ceil(50000/1024)

// Scratch (allocation-free __device__ globals)
__device__ __align__(16) float g_Henc[N_NODES * DIM];        // encoder output (fp32)
__device__ __align__(16) unsigned int g_Hb[N_NODES * DIM/2]; // bf16x2 copy of Henc
__device__ __align__(16) float g_agg [N_NODES * DIM];        // pulled aggregation
__device__ __align__(16) float g_H   [N_NODES * DIM];        // layer output (fp32)
__device__ __align__(16) int   g_deg [N_NODES];              // out-degree over u
__device__ __align__(16) int   g_cnt [N_NODES];              // in-degree over v
__device__ __align__(16) int   g_fill[N_NODES];              // fill cursor per v
__device__ __align__(16) int   g_rowstart[N_NODES + 1];      // CSR row offsets (by v)
__device__ __align__(16) int2  g_uv  [N_EDGES];              // decoded (u,v)
__device__ __align__(16) int2  g_csr [N_EDGES];              // (u, bits(norm)) sorted by v
__device__ __align__(16) float g_sum64[DIM];
__device__ __align__(16) int   g_bsum[SCAN_B];               // per-block cnt sums
__device__ int g_is32;   // 1 if edge_index is int32 on device
__device__ int g_done;   // last-block ticket for fused readout

// ---------------------------------------------------------------------------
// Init: block 0 probes edge_index dtype; all blocks zero counters/sums.
__global__ void __launch_bounds__(256) k_init(const unsigned long long* __restrict__ ei) {
    int i = blockIdx.x * 256 + threadIdx.x;
    if (i < N_NODES) { g_deg[i] = 0; g_cnt[i] = 0; g_fill[i] = 0; }
    if (i < DIM)     g_sum64[i] = 0.f;
    if (i == 0)      g_done = 0;
    if (blockIdx.x == 0) {
        int t = threadIdx.x;
        unsigned int any = 0;
        for (int j = t; j < 2048; j += 256)
            any |= (unsigned int)(ei[j] >> 32);
        __shared__ unsigned int s;
        if (t == 0) s = 0u;
        __syncthreads();
        atomicOr(&s, any);
        __syncthreads();
        if (t == 0) g_is32 = (s != 0u) ? 1 : 0;
    }
}

// Decode edge index -> int2 uv, histogram deg(u) / cnt(v). 2 edges per thread.
__global__ void __launch_bounds__(256) k_prep(const void* __restrict__ eiv) {
    int p = blockIdx.x * 256 + threadIdx.x;       // pair index
    int i = p * 2;
    if (i >= N_EDGES) return;
    int u0, u1, v0, v1;
    if (g_is32) {
        const int2* e = (const int2*)eiv;
        int2 up = e[p];
        int2 vp = ((const int2*)((const int*)eiv + N_EDGES))[p];
        u0 = up.x; u1 = up.y; v0 = vp.x; v1 = vp.y;
    } else {
        const longlong2* e = (const longlong2*)eiv;
        longlong2 up = e[p];
        longlong2 vp = ((const longlong2*)((const long long*)eiv + N_EDGES))[p];
        u0 = (int)up.x; u1 = (int)up.y; v0 = (int)vp.x; v1 = (int)vp.y;
    }
    u0 = min(max(u0, 0), N_NODES - 1); u1 = min(max(u1, 0), N_NODES - 1);
    v0 = min(max(v0, 0), N_NODES - 1); v1 = min(max(v1, 0), N_NODES - 1);
    ((int4*)g_uv)[p] = make_int4(u0, v0, u1, v1);
    atomicAdd(&g_deg[u0], 1);
    atomicAdd(&g_deg[u1], 1);
    atomicAdd(&g_cnt[v0], 1);
    atomicAdd(&g_cnt[v1], 1);
}

// Per-block sums of g_cnt (49 blocks x 1024)
__global__ void __launch_bounds__(1024) k_bsum() {
    int t = threadIdx.x;
    int i = blockIdx.x * 1024 + t;
    int val = (i < N_NODES) ? g_cnt[i] : 0;
#pragma unroll
    for (int o = 16; o; o >>= 1) val += __shfl_xor_sync(0xffffffffu, val, o);
    __shared__ int ws[32];
    if ((t & 31) == 0) ws[t >> 5] = val;
    __syncthreads();
    if (t < 32) {
        int v = ws[t];
#pragma unroll
        for (int o = 16; o; o >>= 1) v += __shfl_xor_sync(0xffffffffu, v, o);
        if (t == 0) g_bsum[blockIdx.x] = v;
    }
}

// Block-local exclusive scan + global base -> g_rowstart
__global__ void __launch_bounds__(1024) k_scan2() {
    int t = threadIdx.x;
    int b = blockIdx.x;
    int i = b * 1024 + t;
    __shared__ int sbase;
    __shared__ int ws[32];
    if (t == 0) {
        int acc = 0;
        for (int j = 0; j < b; j++) acc += g_bsum[j];
        sbase = acc;
    }
    int orig = (i < N_NODES) ? g_cnt[i] : 0;
    int val = orig;
    int lane = t & 31;
#pragma unroll
    for (int o = 1; o < 32; o <<= 1) {
        int n = __shfl_up_sync(0xffffffffu, val, o);
        if (lane >= o) val += n;
    }
    if (lane == 31) ws[t >> 5] = val;
    __syncthreads();
    if (t < 32) {
        int v = ws[t];
#pragma unroll
        for (int o = 1; o < 32; o <<= 1) {
            int n = __shfl_up_sync(0xffffffffu, v, o);
            if (t >= o) v += n;
        }
        ws[t] = v;   // inclusive warp-sums
    }
    __syncthreads();
    int woff = (t >= 32) ? ws[(t >> 5) - 1] : 0;
    int excl = sbase + woff + (val - orig);
    if (i < N_NODES) {
        g_rowstart[i] = excl;
        if (i == N_NODES - 1) g_rowstart[N_NODES] = excl + orig;
    }
}

// Scatter edges into CSR slots (sorted by v); w = ((deg_u+1)(deg_v+1))^-1/2
__global__ void __launch_bounds__(256) k_fill() {
    int i = blockIdx.x * 256 + threadIdx.x;
    if (i >= N_EDGES) return;
    int2 uv = g_uv[i];
    float du = (float)(g_deg[uv.x] + 1);
    float dv = (float)(g_deg[uv.y] + 1);
    float w = rsqrtf(du * dv);
    int pos = g_rowstart[uv.y] + atomicAdd(&g_fill[uv.y], 1);
    g_csr[pos] = make_int2(uv.x, __float_as_int(w));
}

// ---------------------------------------------------------------------------
// Core 64x64 row GEMM: x (16 float4) @ Ws + Bs -> acc (16 float4)
__device__ __forceinline__ void gemm64(
    const float4* __restrict__ x, const float4* __restrict__ Ws,
    const float* __restrict__ Bs, float4* __restrict__ acc)
{
#pragma unroll
    for (int j = 0; j < 16; j++)
        acc[j] = make_float4(Bs[4*j], Bs[4*j+1], Bs[4*j+2], Bs[4*j+3]);
#pragma unroll 1
    for (int kk = 0; kk < 16; kk++) {
        float4 hv = x[kk];
#pragma unroll
        for (int kc = 0; kc < 4; kc++) {
            float hk = (kc == 0) ? hv.x : (kc == 1) ? hv.y : (kc == 2) ? hv.z : hv.w;
            const float4* wrow = Ws + (kk * 4 + kc) * 16;
#pragma unroll
            for (int j = 0; j < 16; j++) {
                float4 w = wrow[j];
                acc[j].x = fmaf(hk, w.x, acc[j].x);
                acc[j].y = fmaf(hk, w.y, acc[j].y);
                acc[j].z = fmaf(hk, w.z, acc[j].z);
                acc[j].w = fmaf(hk, w.w, acc[j].w);
            }
        }
    }
}

// Encoder GEMM: g_Henc/g_Hb = src @ W + b. src = X (layer 0) or g_H.
__global__ void __launch_bounds__(128) k_enc(
    const float* __restrict__ X,
    const float* __restrict__ W,
    const float* __restrict__ B,
    int use_gH)
{
    __shared__ float4 Ws[1024];
    __shared__ float  Bs[64];
    int tid = threadIdx.x;
    const float4* W4 = (const float4*)W;
#pragma unroll
    for (int i = 0; i < 8; i++) Ws[tid + 128 * i] = W4[tid + 128 * i];
    if (tid < 64) Bs[tid] = B[tid];
    __syncthreads();

    int row = blockIdx.x * 128 + tid;
    if (row >= N_NODES) return;
    const float* src = use_gH ? g_H : X;
    float4 acc[16];
    gemm64((const float4*)(src + row * DIM), Ws, Bs, acc);

    float4* o32 = (float4*)(g_Henc + row * DIM);
    uint2*  ob  = (uint2*)(g_Hb + row * (DIM/2));
#pragma unroll
    for (int j = 0; j < 16; j++) {
        float4 v = acc[j];
        o32[j] = v;
        __nv_bfloat162 b0 = __floats2bfloat162_rn(v.x, v.y);
        __nv_bfloat162 b1 = __floats2bfloat162_rn(v.z, v.w);
        ob[j] = make_uint2(*(unsigned int*)&b0, *(unsigned int*)&b1);
    }
}

// Update GEMM: g_H = relu((g_agg + g_Henc) @ W + b)
__global__ void __launch_bounds__(128) k_upd(
    const float* __restrict__ W,
    const float* __restrict__ B)
{
    __shared__ float4 Ws[1024];
    __shared__ float  Bs[64];
    int tid = threadIdx.x;
    const float4* W4 = (const float4*)W;
#pragma unroll
    for (int i = 0; i < 8; i++) Ws[tid + 128 * i] = W4[tid + 128 * i];
    if (tid < 64) Bs[tid] = B[tid];
    __syncthreads();

    int row = blockIdx.x * 128 + tid;
    if (row >= N_NODES) return;

    float4 x[16];
    const float4* hr = (const float4*)(g_Henc + row * DIM);
    const float4* ar = (const float4*)(g_agg  + row * DIM);
#pragma unroll
    for (int j = 0; j < 16; j++) {
        float4 a = hr[j], b = ar[j];
        x[j] = make_float4(a.x + b.x, a.y + b.y, a.z + b.z, a.w + b.w);
    }
    float4 acc[16];
    gemm64(x, Ws, Bs, acc);

    float4* o = (float4*)(g_H + row * DIM);
#pragma unroll
    for (int j = 0; j < 16; j++) {
        float4 v = acc[j];
        v.x = fmaxf(v.x, 0.f); v.y = fmaxf(v.y, 0.f);
        v.z = fmaxf(v.z, 0.f); v.w = fmaxf(v.w, 0.f);
        o[j] = v;
    }
}

// Final update + readout + last-block finalize:
// h = relu((agg+Henc)@Wu+bu); g_sum64 += colsum(h); last block writes out[0].
__global__ void __launch_bounds__(128) k_upd_sum(
    const float* __restrict__ Wu, const float* __restrict__ Bu,
    const float* __restrict__ out_w, const float* __restrict__ out_b,
    float* __restrict__ out)
{
    __shared__ float4 Wsu[1024];
    __shared__ float  Bsu[64];
    __shared__ float  ssum[64];
    int tid = threadIdx.x;
    const float4* Wu4 = (const float4*)Wu;
#pragma unroll
    for (int i = 0; i < 8; i++) Wsu[tid + 128 * i] = Wu4[tid + 128 * i];
    if (tid < 64) { Bsu[tid] = Bu[tid]; ssum[tid] = 0.f; }
    __syncthreads();

    int row = blockIdx.x * 128 + tid;
    bool valid = (row < N_NODES);

    float4 h[16];
    if (valid) {
        float4 x[16];
        const float4* hr = (const float4*)(g_Henc + row * DIM);
        const float4* ar = (const float4*)(g_agg  + row * DIM);
#pragma unroll
        for (int j = 0; j < 16; j++) {
            float4 a = hr[j], b = ar[j];
            x[j] = make_float4(a.x + b.x, a.y + b.y, a.z + b.z, a.w + b.w);
        }
        gemm64(x, Wsu, Bsu, h);
#pragma unroll
        for (int j = 0; j < 16; j++) {
            h[j].x = fmaxf(h[j].x, 0.f); h[j].y = fmaxf(h[j].y, 0.f);
            h[j].z = fmaxf(h[j].z, 0.f); h[j].w = fmaxf(h[j].w, 0.f);
        }
    } else {
#pragma unroll
        for (int j = 0; j < 16; j++) h[j] = make_float4(0.f, 0.f, 0.f, 0.f);
    }

    int lane = tid & 31;
#pragma unroll
    for (int j = 0; j < 16; j++) {
#pragma unroll
        for (int kc = 0; kc < 4; kc++) {
            float v = (kc == 0) ? h[j].x : (kc == 1) ? h[j].y : (kc == 2) ? h[j].z : h[j].w;
#pragma unroll
            for (int o = 16; o; o >>= 1) v += __shfl_xor_sync(0xffffffffu, v, o);
            if (lane == 0) atomicAdd(&ssum[4 * j + kc], v);
        }
    }
    __syncthreads();
    if (tid < 64) atomicAdd(&g_sum64[tid], ssum[tid]);

    // last-block finalize
    __threadfence();
    __shared__ int isLast;
    if (tid == 0) {
        int p = atomicAdd(&g_done, 1);
        isLast = (p == (int)gridDim.x - 1) ? 1 : 0;
    }
    __syncthreads();
    if (isLast && tid < 32) {
        float p = g_sum64[tid] * out_w[tid] + g_sum64[tid + 32] * out_w[tid + 32];
#pragma unroll
        for (int o = 16; o; o >>= 1) p += __shfl_down_sync(0xffffffffu, p, o);
        if (tid == 0) out[0] = p / (float)N_NODES + out_b[0];
    }
}

// ---------------------------------------------------------------------------
// bf16x2-pair FMA helper
__device__ __forceinline__ void bf16fma(float4& a, int wbits, uint2 p) {
    float w = __int_as_float(wbits);
    float2 lo = __bfloat1622float2(*(__nv_bfloat162*)&p.x);
    float2 hi = __bfloat1622float2(*(__nv_bfloat162*)&p.y);
    a.x = fmaf(w, lo.x, a.x); a.y = fmaf(w, lo.y, a.y);
    a.z = fmaf(w, hi.x, a.z); a.w = fmaf(w, hi.y, a.w);
}

// Pull aggregation (bf16 gather, 4 accumulator chains): agg[v] = sum_e w_e*Hb[u_e]
__global__ void __launch_bounds__(256) k_agg() {
    int idx = blockIdx.x * 256 + threadIdx.x;
    int node = idx >> 4;
    if (node >= N_NODES) return;
    int c = idx & 15;
    int s = g_rowstart[node];
    int e = g_rowstart[node + 1];
    const uint2* __restrict__ Hb = (const uint2*)g_Hb;

    float4 a0 = make_float4(0.f, 0.f, 0.f, 0.f);
    float4 a1 = make_float4(0.f, 0.f, 0.f, 0.f);
    float4 a2 = make_float4(0.f, 0.f, 0.f, 0.f);
    float4 a3 = make_float4(0.f, 0.f, 0.f, 0.f);

    int i = s;
    for (; i + 4 <= e; i += 4) {
        int2 e0 = g_csr[i];
        int2 e1 = g_csr[i + 1];
        int2 e2 = g_csr[i + 2];
        int2 e3 = g_csr[i + 3];
        uint2 p0 = Hb[e0.x * 16 + c];
        uint2 p1 = Hb[e1.x * 16 + c];
        uint2 p2 = Hb[e2.x * 16 + c];
        uint2 p3 = Hb[e3.x * 16 + c];
        bf16fma(a0, e0.y, p0);
        bf16fma(a1, e1.y, p1);
        bf16fma(a2, e2.y, p2);
        bf16fma(a3, e3.y, p3);
    }
    for (; i < e; i++) {
        int2 e0 = g_csr[i];
        uint2 p0 = Hb[e0.x * 16 + c];
        bf16fma(a0, e0.y, p0);
    }

    float4 acc;
    acc.x = (a0.x + a1.x) + (a2.x + a3.x);
    acc.y = (a0.y + a1.y) + (a2.y + a3.y);
    acc.z = (a0.z + a1.z) + (a2.z + a3.z);
    acc.w = (a0.w + a1.w) + (a2.w + a3.w);
    ((float4*)g_agg)[node * 16 + c] = acc;
}

// ---------------------------------------------------------------------------
extern "C" void kernel_launch(void* const* d_in, const int* in_sizes, int n_in,
                              void* d_out, int out_size)
{
    const float* H  = (const float*)d_in[0];
    const void*  ei = d_in[1];
    // d_in[2] = E (unused by reference GCN path)
    const float* enc_w[3] = {(const float*)d_in[3],  (const float*)d_in[7],  (const float*)d_in[11]};
    const float* enc_b[3] = {(const float*)d_in[4],  (const float*)d_in[8],  (const float*)d_in[12]};
    const float* upd_w[3] = {(const float*)d_in[5],  (const float*)d_in[9],  (const float*)d_in[13]};
    const float* upd_b[3] = {(const float*)d_in[6],  (const float*)d_in[10], (const float*)d_in[14]};
    const float* out_w = (const float*)d_in[15];
    const float* out_b = (const float*)d_in[16];
    float* out = (float*)d_out;

    const int EB  = (N_EDGES + 255) / 256;            // 4688
    const int PB  = (N_EDGES / 2 + 255) / 256;        // 2344
    const int NB  = (N_NODES + 255) / 256;            // 196
    const int GB  = (N_NODES + 127) / 128;            // 391
    const int AB  = (N_NODES * 16 + 255) / 256;       // 3125

    // Order chosen so launch #4 is k_enc (the kernel ncu captures).
    k_init <<<NB, 256>>>((const unsigned long long*)ei);
    k_prep <<<PB, 256>>>(ei);
    k_bsum <<<SCAN_B, 1024>>>();
    k_enc  <<<GB, 128>>>(H, enc_w[0], enc_b[0], 0);    // 4th launch -> profiled
    k_scan2<<<SCAN_B, 1024>>>();
    k_fill <<<EB, 256>>>();

    k_agg<<<AB, 256>>>();
    k_upd<<<GB, 128>>>(upd_w[0], upd_b[0]);
    k_enc<<<GB, 128>>>(H, enc_w[1], enc_b[1], 1);
    k_agg<<<AB, 256>>>();
    k_upd<<<GB, 128>>>(upd_w[1], upd_b[1]);
    k_enc<<<GB, 128>>>(H, enc_w[2], enc_b[2], 1);
    k_agg<<<AB, 256>>>();
    k_upd_sum<<<GB, 128>>>(upd_w[2], upd_b[2], out_w, out_b, out);
}